// round 2
// baseline (speedup 1.0000x reference)
#include <cuda_runtime.h>
#include <math.h>
#include <stdint.h>

#define BATCH 4096
#define HID   1024
#define INF   (1723*6)   /* 10338 */
#define OUTF  229        /* 24*9 + 10 + 3 */

#define BM 128
#define BN 128
#define BK 16

// ---------------- scratch (static __device__, no allocation) ----------------
__device__ float g_Y[BATCH*HID];
__device__ float g_H[BATCH*HID];
__device__ float g_T[BATCH*HID];
__device__ float g_O[BATCH*OUTF];
__device__ float g_part[2*32*HID];
__device__ float g_scale[HID];
__device__ float g_shift[HID];

// ---------------- packed fp32x2 helpers (Blackwell f32x2 pipe) --------------
__device__ __forceinline__ unsigned long long pack2(float lo, float hi) {
    unsigned long long r;
    asm("mov.b64 %0, {%1, %2};" : "=l"(r) : "f"(lo), "f"(hi));
    return r;
}
__device__ __forceinline__ void unpack2(unsigned long long v, float& lo, float& hi) {
    asm("mov.b64 {%0, %1}, %2;" : "=f"(lo), "=f"(hi) : "l"(v));
}
__device__ __forceinline__ void fma2(unsigned long long& d, unsigned long long a, unsigned long long b) {
    asm("fma.rn.f32x2 %0, %1, %2, %0;" : "+l"(d) : "l"(a), "l"(b));
}

// ---------------- GEMM: Y[M,N] = A[M,K] @ W[K,N] + bias[N] ------------------
// 128x128 block tile, BK=16, 256 threads, 8x8 per-thread microtile computed
// as 8x4 packed f32x2 FMAs. M must be a multiple of 128; N,K arbitrary.
__global__ __launch_bounds__(256, 2)
void sgemm_bias(const float* __restrict__ A, const float* __restrict__ W,
                const float* __restrict__ bias, float* __restrict__ Y,
                int M, int N, int K)
{
    __shared__ __align__(16) float As[BK][BM + 4];
    __shared__ __align__(16) float Bs[BK][BN];

    const int tid  = threadIdx.x;
    const int tm   = tid >> 4;          // 0..15
    const int tn   = tid & 15;          // 0..15
    const int row0 = blockIdx.y * BM;
    const int col0 = blockIdx.x * BN;

    const int a_r = tid >> 1;           // 0..127
    const int a_k = (tid & 1) << 3;     // 0 or 8
    const int b_r = tid >> 4;           // 0..15
    const int b_c = (tid & 15) << 3;    // 0..120

    const bool avec = ((K & 3) == 0);
    const bool bvec = ((N & 3) == 0) && (col0 + BN <= N);

    unsigned long long acc[8][4];
#pragma unroll
    for (int i = 0; i < 8; i++)
#pragma unroll
        for (int j = 0; j < 4; j++) acc[i][j] = 0ull;   // bits 0 == {0.f,0.f}

    for (int k0 = 0; k0 < K; k0 += BK) {
        const bool kfull = (k0 + BK <= K);

        // ---- load A tile (BM x BK), stored transposed As[k][m]
        if (avec && kfull) {
            const float4* Ap = (const float4*)(A + (size_t)(row0 + a_r) * K + (k0 + a_k));
            float4 v0 = Ap[0], v1 = Ap[1];
            As[a_k+0][a_r] = v0.x; As[a_k+1][a_r] = v0.y;
            As[a_k+2][a_r] = v0.z; As[a_k+3][a_r] = v0.w;
            As[a_k+4][a_r] = v1.x; As[a_k+5][a_r] = v1.y;
            As[a_k+6][a_r] = v1.z; As[a_k+7][a_r] = v1.w;
        } else {
            const float* Ap = A + (size_t)(row0 + a_r) * K;
#pragma unroll
            for (int i = 0; i < 8; i++) {
                int kk = k0 + a_k + i;
                As[a_k + i][a_r] = (kk < K) ? Ap[kk] : 0.f;
            }
        }
        // ---- load B tile (BK x BN)
        if (bvec && kfull) {
            const float4* Wp = (const float4*)(W + (size_t)(k0 + b_r) * N + col0 + b_c);
            *(float4*)&Bs[b_r][b_c]     = Wp[0];
            *(float4*)&Bs[b_r][b_c + 4] = Wp[1];
        } else {
            int kk = k0 + b_r;
#pragma unroll
            for (int i = 0; i < 8; i++) {
                int cc = col0 + b_c + i;
                Bs[b_r][b_c + i] = (kk < K && cc < N) ? W[(size_t)kk * N + cc] : 0.f;
            }
        }
        __syncthreads();

#pragma unroll
        for (int k = 0; k < BK; k++) {
            float4 a0 = *(const float4*)&As[k][tm * 8];
            float4 a1 = *(const float4*)&As[k][tm * 8 + 4];
            unsigned long long ad[8];
            ad[0] = pack2(a0.x, a0.x); ad[1] = pack2(a0.y, a0.y);
            ad[2] = pack2(a0.z, a0.z); ad[3] = pack2(a0.w, a0.w);
            ad[4] = pack2(a1.x, a1.x); ad[5] = pack2(a1.y, a1.y);
            ad[6] = pack2(a1.z, a1.z); ad[7] = pack2(a1.w, a1.w);
            const unsigned long long* Bp = (const unsigned long long*)&Bs[k][tn * 8];
            unsigned long long b0 = Bp[0], b1 = Bp[1], b2 = Bp[2], b3 = Bp[3];
#pragma unroll
            for (int i = 0; i < 8; i++) {
                fma2(acc[i][0], ad[i], b0);
                fma2(acc[i][1], ad[i], b1);
                fma2(acc[i][2], ad[i], b2);
                fma2(acc[i][3], ad[i], b3);
            }
        }
        __syncthreads();
    }

    // ---- epilogue: +bias, guarded store
#pragma unroll
    for (int i = 0; i < 8; i++) {
        size_t r = (size_t)(row0 + tm * 8 + i);
#pragma unroll
        for (int j = 0; j < 4; j++) {
            float lo, hi;
            unpack2(acc[i][j], lo, hi);
            int c = col0 + tn * 8 + 2 * j;
            if (c < N)     Y[r * N + c]     = lo + bias[c];
            if (c + 1 < N) Y[r * N + c + 1] = hi + bias[c + 1];
        }
    }
}

// ---------------- BN stats: per-column partial sums over 32 row-slabs -------
__global__ void bn_stats(const float* __restrict__ Y, int M, int N)
{
    int c    = blockIdx.x * blockDim.x + threadIdx.x;   // column
    int slab = blockIdx.y;                              // 0..31
    int rows = M >> 5;
    int r0   = slab * rows;
    float s = 0.f, s2 = 0.f;
    for (int r = r0; r < r0 + rows; r++) {
        float v = Y[(size_t)r * N + c];
        s += v;
        s2 = fmaf(v, v, s2);
    }
    g_part[slab * N + c]          = s;
    g_part[32 * N + slab * N + c] = s2;
}

// ---------------- BN finalize: scale/shift per column -----------------------
__global__ void bn_finalize(const float* __restrict__ g, const float* __restrict__ be,
                            int N, float invM)
{
    int c = blockIdx.x * blockDim.x + threadIdx.x;
    if (c >= N) return;
    float s = 0.f, s2 = 0.f;
#pragma unroll
    for (int i = 0; i < 32; i++) {
        s  += g_part[i * N + c];
        s2 += g_part[32 * N + i * N + c];
    }
    float mu  = s * invM;
    float var = fmaf(-mu, mu, s2 * invM);          // E[y^2]-mu^2 (ddof=0)
    float sc  = g[c] * rsqrtf(var + 1e-5f);
    g_scale[c] = sc;
    g_shift[c] = fmaf(-mu, sc, be[c]);
}

// ---------------- BN apply: H = relu(opt_res + Y*scale + shift) -------------
__global__ void bn_apply(const float* __restrict__ Y, const float* __restrict__ res,
                         float* __restrict__ H, int total, int Nmask)
{
    int i = blockIdx.x * blockDim.x + threadIdx.x;
    if (i >= total) return;
    int c = i & Nmask;
    float v = fmaf(Y[i], g_scale[c], g_shift[c]);
    if (res) v += res[i];
    H[i] = fmaxf(v, 0.f);
}

// ---------------- SO(3) projection: R = sign(det M) * polarfactor(M) --------
// U@Vh from SVD(M) is the orthogonal polar factor; computed via scaled
// Newton iteration  X <- 0.5*(g*X + (1/g)*X^-T),  g = (||X^-1||/||X||)^(1/2).
__global__ void polar_kernel(const float* __restrict__ O, float* __restrict__ out,
                             int total, int ldo)
{
    int idx = blockIdx.x * blockDim.x + threadIdx.x;
    if (idx >= total) return;
    const float* p = O + (size_t)(idx / 24) * ldo + (idx % 24) * 9;

    float X[9];
#pragma unroll
    for (int e = 0; e < 9; e++) X[e] = p[e];

    // sign of det of the original matrix (== det(U@Vh))
    float d0 = X[0]*(X[4]*X[8]-X[5]*X[7]) - X[1]*(X[3]*X[8]-X[5]*X[6])
             + X[2]*(X[3]*X[7]-X[4]*X[6]);
    float sgn = (d0 < 0.f) ? -1.f : 1.f;

#pragma unroll 1
    for (int it = 0; it < 14; it++) {
        float c0 = X[4]*X[8] - X[5]*X[7];
        float c1 = X[5]*X[6] - X[3]*X[8];
        float c2 = X[3]*X[7] - X[4]*X[6];
        float c3 = X[2]*X[7] - X[1]*X[8];
        float c4 = X[0]*X[8] - X[2]*X[6];
        float c5 = X[1]*X[6] - X[0]*X[7];
        float c6 = X[1]*X[5] - X[2]*X[4];
        float c7 = X[2]*X[3] - X[0]*X[5];
        float c8 = X[0]*X[4] - X[1]*X[3];
        float det = X[0]*c0 + X[1]*c1 + X[2]*c2;
        float ad  = fmaxf(fabsf(det), 1e-30f);
        float invdet = (det < 0.f ? -1.f : 1.f) / ad;

        float n1 = X[0]*X[0]+X[1]*X[1]+X[2]*X[2]+X[3]*X[3]+X[4]*X[4]
                 + X[5]*X[5]+X[6]*X[6]+X[7]*X[7]+X[8]*X[8];
        float nc = c0*c0+c1*c1+c2*c2+c3*c3+c4*c4+c5*c5+c6*c6+c7*c7+c8*c8;
        float n2 = nc * invdet * invdet;           // ||X^-1||_F^2
        float gam = sqrtf(sqrtf(n2 / n1));         // (||Xinv||/||X||)^(1/2)
        float hg = 0.5f * gam;
        float hi = 0.5f / gam * invdet;
        X[0] = hg*X[0] + hi*c0;  X[1] = hg*X[1] + hi*c1;  X[2] = hg*X[2] + hi*c2;
        X[3] = hg*X[3] + hi*c3;  X[4] = hg*X[4] + hi*c4;  X[5] = hg*X[5] + hi*c5;
        X[6] = hg*X[6] + hi*c6;  X[7] = hg*X[7] + hi*c7;  X[8] = hg*X[8] + hi*c8;
    }

    float* q = out + (size_t)idx * 9;
#pragma unroll
    for (int e = 0; e < 9; e++) q[e] = sgn * X[e];
}

// ---------------- betas / camera copy ---------------------------------------
__global__ void tail_copy(const float* __restrict__ O, float* __restrict__ out,
                          int Bn, int ldo)
{
    int i = blockIdx.x * blockDim.x + threadIdx.x;
    if (i >= Bn * 13) return;
    int b = i / 13, j = i % 13;
    float v = O[(size_t)b * ldo + 216 + j];
    if (j < 10) out[(size_t)Bn * 216 + (size_t)b * 10 + j] = v;
    else        out[(size_t)Bn * 226 + (size_t)b * 3 + (j - 10)] = v;
}

// ---------------- launch -----------------------------------------------------
extern "C" void kernel_launch(void* const* d_in, const int* in_sizes, int n_in,
                              void* d_out, int out_size)
{
    const float* x   = (const float*)d_in[0];
    const float* w1  = (const float*)d_in[1];
    const float* b1  = (const float*)d_in[2];
    const float* g1  = (const float*)d_in[3];
    const float* be1 = (const float*)d_in[4];
    const float* w2a = (const float*)d_in[5];
    const float* b2a = (const float*)d_in[6];
    const float* g2a = (const float*)d_in[7];
    const float* be2a= (const float*)d_in[8];
    const float* w2b = (const float*)d_in[9];
    const float* b2b = (const float*)d_in[10];
    const float* g2b = (const float*)d_in[11];
    const float* be2b= (const float*)d_in[12];
    const float* w3a = (const float*)d_in[13];
    const float* b3a = (const float*)d_in[14];
    const float* g3a = (const float*)d_in[15];
    const float* be3a= (const float*)d_in[16];
    const float* w3b = (const float*)d_in[17];
    const float* b3b = (const float*)d_in[18];
    const float* g3b = (const float*)d_in[19];
    const float* be3b= (const float*)d_in[20];
    const float* w4  = (const float*)d_in[21];
    const float* b4  = (const float*)d_in[22];

    float *Y, *H, *T, *O;
    cudaGetSymbolAddress((void**)&Y, g_Y);
    cudaGetSymbolAddress((void**)&H, g_H);
    cudaGetSymbolAddress((void**)&T, g_T);
    cudaGetSymbolAddress((void**)&O, g_O);

    auto layer = [&](const float* Ain, const float* Wt, const float* bs,
                     const float* gg, const float* bb, const float* res,
                     float* Hout, int K) {
        dim3 grid(HID / BN, BATCH / BM);
        sgemm_bias<<<grid, 256>>>(Ain, Wt, bs, Y, BATCH, HID, K);
        bn_stats<<<dim3(HID / 256, 32), 256>>>(Y, BATCH, HID);
        bn_finalize<<<HID / 256, 256>>>(gg, bb, HID, 1.f / BATCH);
        bn_apply<<<(BATCH * HID) / 256, 256>>>(Y, res, Hout, BATCH * HID, HID - 1);
    };

    layer(x, w1,  b1,  g1,  be1,  nullptr, H, INF);   // h1 = relu(bn(x@w1))
    layer(H, w2a, b2a, g2a, be2a, nullptr, T, HID);   // t  = relu(bn(h1@w2a))
    layer(T, w2b, b2b, g2b, be2b, H,       H, HID);   // h2 = relu(h1 + bn(t@w2b))
    layer(H, w3a, b3a, g3a, be3a, nullptr, T, HID);
    layer(T, w3b, b3b, g3b, be3b, H,       H, HID);

    sgemm_bias<<<dim3((OUTF + BN - 1) / BN, BATCH / BM), 256>>>(
        H, w4, b4, O, BATCH, OUTF, HID);

    polar_kernel<<<(BATCH * 24 + 255) / 256, 256>>>(O, (float*)d_out, BATCH * 24, OUTF);
    tail_copy<<<(BATCH * 13 + 255) / 256, 256>>>(O, (float*)d_out, BATCH, OUTF);
}

// round 9
// speedup vs baseline: 1.1982x; 1.1982x over previous
#include <cuda_runtime.h>
#include <cuda_bf16.h>
#include <math.h>
#include <stdint.h>

#define BATCH 4096
#define HID   1024
#define INF   (1723*6)   /* 10338 */
#define INFP  10352      /* padded to multiple of 16 */
#define OUTF  229        /* 24*9 + 10 + 3 */

/* ===================== helpers =========================================== */
__device__ __forceinline__ uint32_t smem_to_u32(const void* p) {
    uint32_t a;
    asm("{ .reg .u64 t; cvta.to.shared.u64 t, %1; cvt.u32.u64 %0, t; }"
        : "=r"(a) : "l"(p));
    return a;
}
__device__ __forceinline__ void cp16(uint32_t sm, const void* g) {
    asm volatile("cp.async.cg.shared.global [%0], [%1], 16;"
                 :: "r"(sm), "l"(g));
}
__device__ __forceinline__ uint32_t lds32(uint32_t addr) {
    uint32_t v;
    asm volatile("ld.shared.b32 %0, [%1];" : "=r"(v) : "r"(addr));
    return v;
}
__device__ __forceinline__ float tf32r(float x) {
    uint32_t u;
    asm("cvt.rna.tf32.f32 %0, %1;" : "=r"(u) : "f"(x));
    return __uint_as_float(u);
}
__device__ __forceinline__ void mma_tf32(float* c, const uint32_t* a, const uint32_t* b) {
    asm volatile(
        "mma.sync.aligned.m16n8k8.row.col.f32.tf32.tf32.f32 "
        "{%0,%1,%2,%3}, {%4,%5,%6,%7}, {%8,%9}, {%0,%1,%2,%3};"
        : "+f"(c[0]), "+f"(c[1]), "+f"(c[2]), "+f"(c[3])
        : "r"(a[0]), "r"(a[1]), "r"(a[2]), "r"(a[3]), "r"(b[0]), "r"(b[1]));
}

/* ===================== scratch (static, zero-init) ======================= */
__device__ float g_Y[BATCH*HID];
__device__ float g_H[BATCH*HID];
__device__ float g_T[BATCH*HID];
__device__ float g_O[BATCH*OUTF];
__device__ float g_part[2*32*HID];
__device__ float g_scale[HID];
__device__ float g_shift[HID];

__device__ float g_xhi[(size_t)BATCH*INFP];
__device__ float g_xlo[(size_t)BATCH*INFP];
__device__ float g_w1hi[(size_t)HID*INFP];
__device__ float g_w1lo[(size_t)HID*INFP];
__device__ float g_wbhi[4*(size_t)HID*HID];
__device__ float g_wblo[4*(size_t)HID*HID];
__device__ float g_ahi[2*(size_t)BATCH*HID];
__device__ float g_alo[2*(size_t)BATCH*HID];

/* ===================== conversion kernels ================================ */
__global__ void split_pad(const float* __restrict__ in, float* __restrict__ hi,
                          float* __restrict__ lo, int rows, int K, int KP)
{
    int i = blockIdx.x * blockDim.x + threadIdx.x;
    if (i >= rows * K) return;
    int r = i / K, k = i - r * K;
    float v = in[i];
    float h = tf32r(v);
    size_t o = (size_t)r * KP + k;
    hi[o] = h;
    lo[o] = tf32r(v - h);
}

// W [K,N] -> out [N,KP] tf32 hi/lo (transposed split)
__global__ void transpose_split(const float* __restrict__ W,
                                float* __restrict__ Thi, float* __restrict__ Tlo,
                                int K, int N, int KP)
{
    __shared__ float t[32][33];
    int kb = blockIdx.y * 32, nb = blockIdx.x * 32;
    int tx = threadIdx.x, ty = threadIdx.y;       // 32 x 8
#pragma unroll
    for (int i = ty; i < 32; i += 8) {
        int k = kb + i, n = nb + tx;
        t[i][tx] = (k < K && n < N) ? W[(size_t)k * N + n] : 0.f;
    }
    __syncthreads();
#pragma unroll
    for (int i = ty; i < 32; i += 8) {
        int n = nb + i, k = kb + tx;
        if (n < N && k < K) {
            float v = t[tx][i];
            float h = tf32r(v);
            size_t o = (size_t)n * KP + k;
            Thi[o] = h;
            Tlo[o] = tf32r(v - h);
        }
    }
}

/* ===================== tf32x3 HMMA GEMM (two-stage accumulate) =========== */
// Y[M,N] = A @ B^T + bias; A [M,K] tf32 hi/lo (fp32 storage), B [N,K] ditto.
// K % 16 == 0. Tile 128x128x16, 256 threads, warp tile 64x32, double-buffered.
// Accumulation: per-chunk small accumulator (tensor-core RZ span = 6 adds),
// flushed into master fp32 accumulator with RNE FADD each chunk.
#define APITCH 20                      /* row pitch in floats (80 B) */
#define TILEF  (128*APITCH*4)          /* 10240 B per tile */
#define BUFB   (4*TILEF)               /* Ahi,Alo,Bhi,Blo */
#define GSMEM  (2*BUFB)                /* 81920 B */

__device__ __forceinline__ void load_chunk(uint32_t dst,
    const float* __restrict__ Ahi, const float* __restrict__ Alo,
    const float* __restrict__ Bhi, const float* __restrict__ Blo,
    int row0, int col0, int K, int k0, int tid)
{
#pragma unroll
    for (int i = 0; i < 2; i++) {
        int idx = tid + i * 256;            // 0..511
        int r   = idx >> 2;                 // 0..127
        int seg = (idx & 3) << 4;           // 0,16,32,48 bytes
        uint32_t so = (uint32_t)(r * 80 + seg);
        const char* pa = (const char*)(Ahi + (size_t)(row0 + r) * K + k0) + seg;
        const char* pl = (const char*)(Alo + (size_t)(row0 + r) * K + k0) + seg;
        const char* pb = (const char*)(Bhi + (size_t)(col0 + r) * K + k0) + seg;
        const char* pc = (const char*)(Blo + (size_t)(col0 + r) * K + k0) + seg;
        cp16(dst + so,             pa);
        cp16(dst + TILEF + so,     pl);
        cp16(dst + 2*TILEF + so,   pb);
        cp16(dst + 3*TILEF + so,   pc);
    }
}

__global__ __launch_bounds__(256, 1)
void gemm_tf32x3(const float* __restrict__ Ahi, const float* __restrict__ Alo,
                 const float* __restrict__ Bhi, const float* __restrict__ Blo,
                 const float* __restrict__ bias, float* __restrict__ Y, int N, int K)
{
    extern __shared__ char smem[];
    uint32_t sb = smem_to_u32(smem);
    const int tid = threadIdx.x, lane = tid & 31, wid = tid >> 5;
    const int wm = wid >> 2, wn = wid & 3;           // 2 x 4 warp grid
    const int row0 = blockIdx.y * 128, col0 = blockIdx.x * 128;

    float C[4][4][4];    // master accumulator (RNE merges)
    float Cs[4][4][4];   // per-chunk tensor-core accumulator (RZ span small)
#pragma unroll
    for (int i = 0; i < 4; i++)
#pragma unroll
        for (int j = 0; j < 4; j++)
#pragma unroll
            for (int q = 0; q < 4; q++) { C[i][j][q] = 0.f; Cs[i][j][q] = 0.f; }

    const int grp = lane >> 2;         // 0..7
    const int tig = lane & 3;          // 0..3

    load_chunk(sb, Ahi, Alo, Bhi, Blo, row0, col0, K, 0, tid);
    asm volatile("cp.async.commit_group;");

    const int nch = K >> 4;
    for (int c = 0; c < nch; c++) {
        if (c + 1 < nch) {
            load_chunk(sb + ((c + 1) & 1) * BUFB, Ahi, Alo, Bhi, Blo,
                       row0, col0, K, (c + 1) << 4, tid);
            asm volatile("cp.async.commit_group;");
            asm volatile("cp.async.wait_group 1;");
        } else {
            asm volatile("cp.async.wait_group 0;");
        }
        __syncthreads();
        uint32_t base = sb + (c & 1) * BUFB;
#pragma unroll
        for (int ks = 0; ks < 16; ks += 8) {
            uint32_t ah[4][4], al[4][4], bh[4][2], bl[4][2];
#pragma unroll
            for (int mt = 0; mt < 4; mt++) {
                uint32_t a0 = base + (uint32_t)((wm * 64 + mt * 16 + grp) * APITCH + ks + tig) * 4;
                ah[mt][0] = lds32(a0);
                ah[mt][1] = lds32(a0 + 8 * APITCH * 4);
                ah[mt][2] = lds32(a0 + 16);
                ah[mt][3] = lds32(a0 + 8 * APITCH * 4 + 16);
                al[mt][0] = lds32(a0 + TILEF);
                al[mt][1] = lds32(a0 + TILEF + 8 * APITCH * 4);
                al[mt][2] = lds32(a0 + TILEF + 16);
                al[mt][3] = lds32(a0 + TILEF + 8 * APITCH * 4 + 16);
            }
#pragma unroll
            for (int nt = 0; nt < 4; nt++) {
                uint32_t b0 = base + 2 * TILEF +
                              (uint32_t)((wn * 32 + nt * 8 + grp) * APITCH + ks + tig) * 4;
                bh[nt][0] = lds32(b0);
                bh[nt][1] = lds32(b0 + 16);
                bl[nt][0] = lds32(b0 + TILEF);
                bl[nt][1] = lds32(b0 + TILEF + 16);
            }
#pragma unroll
            for (int mt = 0; mt < 4; mt++) {
#pragma unroll
                for (int nt = 0; nt < 4; nt++) {
                    mma_tf32(Cs[mt][nt], ah[mt], bh[nt]);
                    mma_tf32(Cs[mt][nt], al[mt], bh[nt]);
                    mma_tf32(Cs[mt][nt], ah[mt], bl[nt]);
                }
            }
        }
        // flush small accumulator into master with RNE adds (limits RZ span)
#pragma unroll
        for (int mt = 0; mt < 4; mt++)
#pragma unroll
            for (int nt = 0; nt < 4; nt++)
#pragma unroll
                for (int q = 0; q < 4; q++) {
                    C[mt][nt][q] += Cs[mt][nt][q];
                    Cs[mt][nt][q] = 0.f;
                }
        __syncthreads();
    }

    // epilogue: + bias, fp32 store
#pragma unroll
    for (int mt = 0; mt < 4; mt++) {
        int r0 = row0 + wm * 64 + mt * 16 + grp;
#pragma unroll
        for (int nt = 0; nt < 4; nt++) {
            int col = col0 + wn * 32 + nt * 8 + tig * 2;
            float b0 = bias[col], b1 = bias[col + 1];
            float2 v0 = make_float2(C[mt][nt][0] + b0, C[mt][nt][1] + b1);
            float2 v1 = make_float2(C[mt][nt][2] + b0, C[mt][nt][3] + b1);
            *(float2*)&Y[(size_t)r0 * N + col]       = v0;
            *(float2*)&Y[(size_t)(r0 + 8) * N + col] = v1;
        }
    }
}

/* ===================== fp32 GEMM (final small layer) ===================== */
#define BM 128
#define BN 128
#define BK 16
__device__ __forceinline__ unsigned long long pack2(float lo, float hi) {
    unsigned long long r;
    asm("mov.b64 %0, {%1, %2};" : "=l"(r) : "f"(lo), "f"(hi));
    return r;
}
__device__ __forceinline__ void unpack2(unsigned long long v, float& lo, float& hi) {
    asm("mov.b64 {%0, %1}, %2;" : "=f"(lo), "=f"(hi) : "l"(v));
}
__device__ __forceinline__ void fma2(unsigned long long& d, unsigned long long a, unsigned long long b) {
    asm("fma.rn.f32x2 %0, %1, %2, %0;" : "+l"(d) : "l"(a), "l"(b));
}
__global__ __launch_bounds__(256, 2)
void sgemm_bias(const float* __restrict__ A, const float* __restrict__ W,
                const float* __restrict__ bias, float* __restrict__ Y,
                int M, int N, int K)
{
    __shared__ __align__(16) float As[BK][BM + 4];
    __shared__ __align__(16) float Bs[BK][BN];
    const int tid = threadIdx.x;
    const int tm = tid >> 4, tn = tid & 15;
    const int row0 = blockIdx.y * BM, col0 = blockIdx.x * BN;
    const int a_r = tid >> 1, a_k = (tid & 1) << 3;
    const int b_r = tid >> 4, b_c = (tid & 15) << 3;
    const bool avec = ((K & 3) == 0);
    const bool bvec = ((N & 3) == 0) && (col0 + BN <= N);
    unsigned long long acc[8][4];
#pragma unroll
    for (int i = 0; i < 8; i++)
#pragma unroll
        for (int j = 0; j < 4; j++) acc[i][j] = 0ull;
    for (int k0 = 0; k0 < K; k0 += BK) {
        const bool kfull = (k0 + BK <= K);
        if (avec && kfull) {
            const float4* Ap = (const float4*)(A + (size_t)(row0 + a_r) * K + (k0 + a_k));
            float4 v0 = Ap[0], v1 = Ap[1];
            As[a_k+0][a_r] = v0.x; As[a_k+1][a_r] = v0.y;
            As[a_k+2][a_r] = v0.z; As[a_k+3][a_r] = v0.w;
            As[a_k+4][a_r] = v1.x; As[a_k+5][a_r] = v1.y;
            As[a_k+6][a_r] = v1.z; As[a_k+7][a_r] = v1.w;
        } else {
            const float* Ap = A + (size_t)(row0 + a_r) * K;
#pragma unroll
            for (int i = 0; i < 8; i++) {
                int kk = k0 + a_k + i;
                As[a_k + i][a_r] = (kk < K) ? Ap[kk] : 0.f;
            }
        }
        if (bvec && kfull) {
            const float4* Wp = (const float4*)(W + (size_t)(k0 + b_r) * N + col0 + b_c);
            *(float4*)&Bs[b_r][b_c]     = Wp[0];
            *(float4*)&Bs[b_r][b_c + 4] = Wp[1];
        } else {
            int kk = k0 + b_r;
#pragma unroll
            for (int i = 0; i < 8; i++) {
                int cc = col0 + b_c + i;
                Bs[b_r][b_c + i] = (kk < K && cc < N) ? W[(size_t)kk * N + cc] : 0.f;
            }
        }
        __syncthreads();
#pragma unroll
        for (int k = 0; k < BK; k++) {
            float4 a0 = *(const float4*)&As[k][tm * 8];
            float4 a1 = *(const float4*)&As[k][tm * 8 + 4];
            unsigned long long ad[8];
            ad[0] = pack2(a0.x, a0.x); ad[1] = pack2(a0.y, a0.y);
            ad[2] = pack2(a0.z, a0.z); ad[3] = pack2(a0.w, a0.w);
            ad[4] = pack2(a1.x, a1.x); ad[5] = pack2(a1.y, a1.y);
            ad[6] = pack2(a1.z, a1.z); ad[7] = pack2(a1.w, a1.w);
            const unsigned long long* Bp = (const unsigned long long*)&Bs[k][tn * 8];
            unsigned long long b0 = Bp[0], b1 = Bp[1], b2 = Bp[2], b3 = Bp[3];
#pragma unroll
            for (int i = 0; i < 8; i++) {
                fma2(acc[i][0], ad[i], b0);
                fma2(acc[i][1], ad[i], b1);
                fma2(acc[i][2], ad[i], b2);
                fma2(acc[i][3], ad[i], b3);
            }
        }
        __syncthreads();
    }
#pragma unroll
    for (int i = 0; i < 8; i++) {
        size_t r = (size_t)(row0 + tm * 8 + i);
#pragma unroll
        for (int j = 0; j < 4; j++) {
            float lo, hi;
            unpack2(acc[i][j], lo, hi);
            int c = col0 + tn * 8 + 2 * j;
            if (c < N)     Y[r * N + c]     = lo + bias[c];
            if (c + 1 < N) Y[r * N + c + 1] = hi + bias[c + 1];
        }
    }
}

/* ===================== BN kernels ======================================== */
__global__ void bn_stats(const float* __restrict__ Y, int M, int N)
{
    int c = blockIdx.x * blockDim.x + threadIdx.x;
    int slab = blockIdx.y;
    int rows = M >> 5;
    int r0 = slab * rows;
    float s = 0.f, s2 = 0.f;
    for (int r = r0; r < r0 + rows; r++) {
        float v = Y[(size_t)r * N + c];
        s += v;
        s2 = fmaf(v, v, s2);
    }
    g_part[slab * N + c]          = s;
    g_part[32 * N + slab * N + c] = s2;
}
__global__ void bn_finalize(const float* __restrict__ g, const float* __restrict__ be,
                            int N, float invM)
{
    int c = blockIdx.x * blockDim.x + threadIdx.x;
    if (c >= N) return;
    float s = 0.f, s2 = 0.f;
#pragma unroll
    for (int i = 0; i < 32; i++) {
        s  += g_part[i * N + c];
        s2 += g_part[32 * N + i * N + c];
    }
    float mu  = s * invM;
    float var = fmaf(-mu, mu, s2 * invM);
    float sc  = g[c] * rsqrtf(var + 1e-5f);
    g_scale[c] = sc;
    g_shift[c] = fmaf(-mu, sc, be[c]);
}
__global__ void bn_apply(const float* __restrict__ Y, const float* __restrict__ res,
                         float* __restrict__ H, float* __restrict__ Hhi,
                         float* __restrict__ Hlo, int total, int Nmask)
{
    int i = blockIdx.x * blockDim.x + threadIdx.x;
    if (i >= total) return;
    int c = i & Nmask;
    float v = fmaf(Y[i], g_scale[c], g_shift[c]);
    if (res) v += res[i];
    v = fmaxf(v, 0.f);
    H[i] = v;
    if (Hhi) {
        float h = tf32r(v);
        Hhi[i] = h;
        Hlo[i] = tf32r(v - h);
    }
}

/* ===================== SO(3) projection ================================== */
__global__ void polar_kernel(const float* __restrict__ O, float* __restrict__ out,
                             int total, int ldo)
{
    int idx = blockIdx.x * blockDim.x + threadIdx.x;
    if (idx >= total) return;
    const float* p = O + (size_t)(idx / 24) * ldo + (idx % 24) * 9;
    float X[9];
#pragma unroll
    for (int e = 0; e < 9; e++) X[e] = p[e];
    float d0 = X[0]*(X[4]*X[8]-X[5]*X[7]) - X[1]*(X[3]*X[8]-X[5]*X[6])
             + X[2]*(X[3]*X[7]-X[4]*X[6]);
    float sgn = (d0 < 0.f) ? -1.f : 1.f;
#pragma unroll 1
    for (int it = 0; it < 14; it++) {
        float c0 = X[4]*X[8] - X[5]*X[7];
        float c1 = X[5]*X[6] - X[3]*X[8];
        float c2 = X[3]*X[7] - X[4]*X[6];
        float c3 = X[2]*X[7] - X[1]*X[8];
        float c4 = X[0]*X[8] - X[2]*X[6];
        float c5 = X[1]*X[6] - X[0]*X[7];
        float c6 = X[1]*X[5] - X[2]*X[4];
        float c7 = X[2]*X[3] - X[0]*X[5];
        float c8 = X[0]*X[4] - X[1]*X[3];
        float det = X[0]*c0 + X[1]*c1 + X[2]*c2;
        float ad  = fmaxf(fabsf(det), 1e-30f);
        float invdet = (det < 0.f ? -1.f : 1.f) / ad;
        float n1 = X[0]*X[0]+X[1]*X[1]+X[2]*X[2]+X[3]*X[3]+X[4]*X[4]
                 + X[5]*X[5]+X[6]*X[6]+X[7]*X[7]+X[8]*X[8];
        float nc = c0*c0+c1*c1+c2*c2+c3*c3+c4*c4+c5*c5+c6*c6+c7*c7+c8*c8;
        float n2 = nc * invdet * invdet;
        float gam = sqrtf(sqrtf(n2 / n1));
        float hg = 0.5f * gam;
        float hi = 0.5f / gam * invdet;
        X[0] = hg*X[0] + hi*c0;  X[1] = hg*X[1] + hi*c1;  X[2] = hg*X[2] + hi*c2;
        X[3] = hg*X[3] + hi*c3;  X[4] = hg*X[4] + hi*c4;  X[5] = hg*X[5] + hi*c5;
        X[6] = hg*X[6] + hi*c6;  X[7] = hg*X[7] + hi*c7;  X[8] = hg*X[8] + hi*c8;
    }
    float* q = out + (size_t)idx * 9;
#pragma unroll
    for (int e = 0; e < 9; e++) q[e] = sgn * X[e];
}
__global__ void tail_copy(const float* __restrict__ O, float* __restrict__ out,
                          int Bn, int ldo)
{
    int i = blockIdx.x * blockDim.x + threadIdx.x;
    if (i >= Bn * 13) return;
    int b = i / 13, j = i % 13;
    float v = O[(size_t)b * ldo + 216 + j];
    if (j < 10) out[(size_t)Bn * 216 + (size_t)b * 10 + j] = v;
    else        out[(size_t)Bn * 226 + (size_t)b * 3 + (j - 10)] = v;
}

/* ===================== launch ============================================ */
extern "C" void kernel_launch(void* const* d_in, const int* in_sizes, int n_in,
                              void* d_out, int out_size)
{
    const float* x   = (const float*)d_in[0];
    const float* w1  = (const float*)d_in[1];
    const float* b1  = (const float*)d_in[2];
    const float* g1  = (const float*)d_in[3];
    const float* be1 = (const float*)d_in[4];
    const float* w2a = (const float*)d_in[5];
    const float* b2a = (const float*)d_in[6];
    const float* g2a = (const float*)d_in[7];
    const float* be2a= (const float*)d_in[8];
    const float* w2b = (const float*)d_in[9];
    const float* b2b = (const float*)d_in[10];
    const float* g2b = (const float*)d_in[11];
    const float* be2b= (const float*)d_in[12];
    const float* w3a = (const float*)d_in[13];
    const float* b3a = (const float*)d_in[14];
    const float* g3a = (const float*)d_in[15];
    const float* be3a= (const float*)d_in[16];
    const float* w3b = (const float*)d_in[17];
    const float* b3b = (const float*)d_in[18];
    const float* g3b = (const float*)d_in[19];
    const float* be3b= (const float*)d_in[20];
    const float* w4  = (const float*)d_in[21];
    const float* b4  = (const float*)d_in[22];

    float *Y, *H, *T, *O;
    cudaGetSymbolAddress((void**)&Y, g_Y);
    cudaGetSymbolAddress((void**)&H, g_H);
    cudaGetSymbolAddress((void**)&T, g_T);
    cudaGetSymbolAddress((void**)&O, g_O);
    float *xhi, *xlo, *w1hi, *w1lo, *wbhi, *wblo, *ahi, *alo;
    cudaGetSymbolAddress((void**)&xhi,  g_xhi);
    cudaGetSymbolAddress((void**)&xlo,  g_xlo);
    cudaGetSymbolAddress((void**)&w1hi, g_w1hi);
    cudaGetSymbolAddress((void**)&w1lo, g_w1lo);
    cudaGetSymbolAddress((void**)&wbhi, g_wbhi);
    cudaGetSymbolAddress((void**)&wblo, g_wblo);
    cudaGetSymbolAddress((void**)&ahi,  g_ahi);
    cudaGetSymbolAddress((void**)&alo,  g_alo);

    cudaFuncSetAttribute(gemm_tf32x3, cudaFuncAttributeMaxDynamicSharedMemorySize, GSMEM);

    // ---- weight / input conversions
    split_pad<<<(BATCH * INF + 255) / 256, 256>>>(x, xhi, xlo, BATCH, INF, INFP);
    transpose_split<<<dim3(HID / 32, (INF + 31) / 32), dim3(32, 8)>>>(w1, w1hi, w1lo, INF, HID, INFP);
    const float* wres[4] = {w2a, w2b, w3a, w3b};
    for (int i = 0; i < 4; i++)
        transpose_split<<<dim3(HID / 32, HID / 32), dim3(32, 8)>>>(
            wres[i], wbhi + (size_t)i * HID * HID, wblo + (size_t)i * HID * HID, HID, HID, HID);

    const size_t AS = (size_t)BATCH * HID;
    dim3 ggrid(HID / 128, BATCH / 128);

    auto bn = [&](const float* gg, const float* bb, const float* res,
                  float* Hout, float* hh, float* ll) {
        bn_stats<<<dim3(HID / 256, 32), 256>>>(Y, BATCH, HID);
        bn_finalize<<<HID / 256, 256>>>(gg, bb, HID, 1.f / BATCH);
        bn_apply<<<(BATCH * HID) / 256, 256>>>(Y, res, Hout, hh, ll, BATCH * HID, HID - 1);
    };

    // L1: h1 = relu(bn(x@w1))          -> H fp32, act0 split
    gemm_tf32x3<<<ggrid, 256, GSMEM>>>(xhi, xlo, w1hi, w1lo, b1, Y, HID, INFP);
    bn(g1, be1, nullptr, H, ahi, alo);
    // L2a: t = relu(bn(h1@w2a))        -> T fp32, act1 split
    gemm_tf32x3<<<ggrid, 256, GSMEM>>>(ahi, alo, wbhi, wblo, b2a, Y, HID, HID);
    bn(g2a, be2a, nullptr, T, ahi + AS, alo + AS);
    // L2b: h2 = relu(h1 + bn(t@w2b))   -> H fp32, act0 split
    gemm_tf32x3<<<ggrid, 256, GSMEM>>>(ahi + AS, alo + AS,
                                       wbhi + (size_t)1 * HID * HID, wblo + (size_t)1 * HID * HID,
                                       b2b, Y, HID, HID);
    bn(g2b, be2b, H, H, ahi, alo);
    // L3a
    gemm_tf32x3<<<ggrid, 256, GSMEM>>>(ahi, alo,
                                       wbhi + (size_t)2 * HID * HID, wblo + (size_t)2 * HID * HID,
                                       b3a, Y, HID, HID);
    bn(g3a, be3a, nullptr, T, ahi + AS, alo + AS);
    // L3b: final h -> H fp32 only
    gemm_tf32x3<<<ggrid, 256, GSMEM>>>(ahi + AS, alo + AS,
                                       wbhi + (size_t)3 * HID * HID, wblo + (size_t)3 * HID * HID,
                                       b3b, Y, HID, HID);
    bn(g3b, be3b, H, H, nullptr, nullptr);

    // L4 small fp32 GEMM (exact path)
    sgemm_bias<<<dim3((OUTF + BN - 1) / BN, BATCH / BM), 256>>>(H, w4, b4, O, BATCH, OUTF, HID);

    polar_kernel<<<(BATCH * 24 + 255) / 256, 256>>>(O, (float*)d_out, BATCH * 24, OUTF);
    tail_copy<<<(BATCH * 13 + 255) / 256, 256>>>(O, (float*)d_out, BATCH, OUTF);
}